// round 12
// baseline (speedup 1.0000x reference)
#include <cuda_runtime.h>
#include <cstdint>

#define N_NODES 100000
#define N_EDGES 1000000
#define D 64
#define CAP 64           // padded CSR slots/node (Poisson(10): P(deg>64)~1e-30; fallback exists)

// Scratch (device globals — no allocations allowed)
__device__ __align__(16) float g_mean[N_NODES * D];
__device__ int g_cnt[N_NODES];
__device__ __align__(16) int g_csr[N_NODES * CAP];

// ---------------------------------------------------------------------------
// Kernel 1: zero degree counters
// ---------------------------------------------------------------------------
__global__ __launch_bounds__(256) void zero_kernel() {
    const int i = blockIdx.x * 256 + threadIdx.x;
    if (i < N_NODES) g_cnt[i] = 0;
}

// ---------------------------------------------------------------------------
// Kernel 2: CSR fill (1 edge/thread — measured best)
// ---------------------------------------------------------------------------
__global__ __launch_bounds__(256) void fill_kernel(const int* __restrict__ ei) {
    const int e = blockIdx.x * 256 + threadIdx.x;
    if (e >= N_EDGES) return;
    const int dst = __ldg(ei + N_EDGES + e);
    const int src = __ldg(ei + e);
    const int pos = atomicAdd(g_cnt + dst, 1);
    if (pos < CAP) g_csr[dst * CAP + pos] = src;
}

// ---------------------------------------------------------------------------
// Kernel 3: gather (round-5 form). Half-warp per node, LDG.128 streams,
// register accumulation, single mean-row write. Inline overflow fallback.
// ---------------------------------------------------------------------------
__global__ __launch_bounds__(256) void gather_kernel(const float* __restrict__ x,
                                                     const int* __restrict__ ei) {
    const int warp = blockIdx.x * 8 + (threadIdx.x >> 5);
    const int lane = threadIdx.x & 31;
    const int sub  = lane >> 4;
    const int j    = lane & 15;
    const int node = warp * 2 + sub;      // grid covers exactly N_NODES

    const int cnt  = g_cnt[node];
    const float r  = 1.0f / (float)(cnt > 1 ? cnt : 1);
    const float4* x4 = reinterpret_cast<const float4*>(x);

    float4 acc = make_float4(0.f, 0.f, 0.f, 0.f);
    if (cnt <= CAP) {
        const int4* row = reinterpret_cast<const int4*>(g_csr + node * CAP);
        for (int e0 = 0; e0 < cnt; e0 += 4) {
            const int4 s = __ldg(row + (e0 >> 2));   // broadcast in half-warp
            const int rem = cnt - e0;
            float4 v0 = __ldg(x4 + (size_t)s.x * 16 + j);
            float4 v1, v2, v3;
            if (rem > 1) v1 = __ldg(x4 + (size_t)s.y * 16 + j);
            if (rem > 2) v2 = __ldg(x4 + (size_t)s.z * 16 + j);
            if (rem > 3) v3 = __ldg(x4 + (size_t)s.w * 16 + j);
            acc.x += v0.x; acc.y += v0.y; acc.z += v0.z; acc.w += v0.w;
            if (rem > 1) { acc.x += v1.x; acc.y += v1.y; acc.z += v1.z; acc.w += v1.w; }
            if (rem > 2) { acc.x += v2.x; acc.y += v2.y; acc.z += v2.z; acc.w += v2.w; }
            if (rem > 3) { acc.x += v3.x; acc.y += v3.y; acc.z += v3.z; acc.w += v3.w; }
        }
    } else {
        for (int e = 0; e < N_EDGES; e++) {          // ~never taken
            if (__ldg(ei + N_EDGES + e) == node) {
                float4 v = __ldg(x4 + (size_t)__ldg(ei + e) * 16 + j);
                acc.x += v.x; acc.y += v.y; acc.z += v.z; acc.w += v.w;
            }
        }
    }
    acc.x *= r; acc.y *= r; acc.z *= r; acc.w *= r;
    reinterpret_cast<float4*>(g_mean)[(size_t)node * 16 + j] = acc;
}

// ---------------------------------------------------------------------------
// Kernel 4: out = relu([mean|x] @ [Wl;Wr]^T + b), single K=128 GEMM.
// 256 threads / 128-node block. k-SPLIT: kz=0 handles k<64, kz=1 handles
// k>=64; each computes a partial 8-node x 8-out tile (packed f32x2), then
// kz=1 spills partials to smem (reusing sW) and kz=0 reduces + stores.
// Per thread per k: 64B LDS for 32 FFMA2 -> LDS demand ~= fma floor.
// ---------------------------------------------------------------------------
#define WPAD 68      // 64 + 4
#define APAD 132     // 128 + 4
#define K2   128

__global__ __launch_bounds__(256, 2) void out_kernel(
    const float* __restrict__ x,
    const float* __restrict__ Wl,
    const float* __restrict__ bl,
    const float* __restrict__ Wr,
    float* __restrict__ out)
{
    extern __shared__ float sm[];
    float* sW  = sm;                        // [128][WPAD]: k<64 -> Wl, k>=64 -> Wr
    float* sAX = sW + K2 * WPAD;            // [128][APAD]: k<64 -> mean, k>=64 -> x

    const int tid = threadIdx.x;
    const int node0 = blockIdx.x * 128;

    // --- staging: threads 0..127 stage AX (one node each); 128..191 stage W ---
    if (tid < 128) {
        const int gn = node0 + tid;
        const bool ok = gn < N_NODES;
        const float4* m4  = reinterpret_cast<const float4*>(g_mean) + (size_t)(ok ? gn : 0) * 16;
        const float4* xv4 = reinterpret_cast<const float4*>(x)      + (size_t)(ok ? gn : 0) * 16;
        #pragma unroll 4
        for (int kq = 0; kq < 16; kq++) {
            float4 a = __ldg(m4 + kq);
            float4 v = __ldg(xv4 + kq);
            if (!ok) { a = make_float4(0.f,0.f,0.f,0.f); v = a; }
            const int k = kq * 4;
            sAX[(k+0)*APAD + tid] = a.x; sAX[(k+1)*APAD + tid] = a.y;
            sAX[(k+2)*APAD + tid] = a.z; sAX[(k+3)*APAD + tid] = a.w;
            sAX[(64+k+0)*APAD + tid] = v.x; sAX[(64+k+1)*APAD + tid] = v.y;
            sAX[(64+k+2)*APAD + tid] = v.z; sAX[(64+k+3)*APAD + tid] = v.w;
        }
    } else if (tid < 192) {
        const int o = tid - 128;            // 0..63: output row of Wl/Wr
        const float4* wl4 = reinterpret_cast<const float4*>(Wl + o * D);
        const float4* wr4 = reinterpret_cast<const float4*>(Wr + o * D);
        #pragma unroll 4
        for (int kq = 0; kq < 16; kq++) {
            const float4 w = __ldg(wl4 + kq);
            const float4 u = __ldg(wr4 + kq);
            const int k = kq * 4;
            sW[(k+0)*WPAD + o] = w.x; sW[(k+1)*WPAD + o] = w.y;
            sW[(k+2)*WPAD + o] = w.z; sW[(k+3)*WPAD + o] = w.w;
            sW[(64+k+0)*WPAD + o] = u.x; sW[(64+k+1)*WPAD + o] = u.y;
            sW[(64+k+2)*WPAD + o] = u.z; sW[(64+k+3)*WPAD + o] = u.w;
        }
    }
    __syncthreads();

    // --- GEMM: kz picks the k-half; (tx,ty) picks the 8x8 tile ---
    const int kz = tid >> 7;                // 0 or 1
    const int t  = tid & 127;
    const int tx = t & 7;
    const int ty = t >> 3;                  // 0..15
    const int ob = tx * 8;
    const int nb = ty * 8;
    const int kbase = kz * 64;

    unsigned long long acc[4][8];           // [node-pair][out]
    if (kz == 0) {                          // bias only once (kz=0 half)
        #pragma unroll
        for (int o = 0; o < 8; o++) {
            const float b = __ldg(bl + ob + o);
            unsigned long long bp;
            asm("mov.b64 %0, {%1, %2};" : "=l"(bp) : "f"(b), "f"(b));
            #pragma unroll
            for (int m = 0; m < 4; m++) acc[m][o] = bp;
        }
    } else {
        #pragma unroll
        for (int o = 0; o < 8; o++)
            #pragma unroll
            for (int m = 0; m < 4; m++) acc[m][o] = 0ull;
    }

    #pragma unroll 4
    for (int k = 0; k < 64; k++) {
        const int kk = kbase + k;
        const ulonglong2 aA = *reinterpret_cast<const ulonglong2*>(sAX + kk*APAD + nb);
        const ulonglong2 aB = *reinterpret_cast<const ulonglong2*>(sAX + kk*APAD + nb + 4);
        const float4 w0 = *reinterpret_cast<const float4*>(sW + kk*WPAD + ob);
        const float4 w1 = *reinterpret_cast<const float4*>(sW + kk*WPAD + ob + 4);
        const unsigned long long ap[4] = {aA.x, aA.y, aB.x, aB.y};
        const float wv[8] = {w0.x, w0.y, w0.z, w0.w, w1.x, w1.y, w1.z, w1.w};
        #pragma unroll
        for (int o = 0; o < 8; o++) {
            unsigned long long w2;
            asm("mov.b64 %0, {%1, %2};" : "=l"(w2) : "f"(wv[o]), "f"(wv[o]));
            #pragma unroll
            for (int m = 0; m < 4; m++)
                asm("fma.rn.f32x2 %0, %1, %2, %0;" : "+l"(acc[m][o]) : "l"(ap[m]), "l"(w2));
        }
    }

    // --- cross-kz reduction: kz=1 spills partials into sW region (32KB) ---
    __syncthreads();                        // mainloop done; sW free to reuse
    unsigned long long* sP = reinterpret_cast<unsigned long long*>(sW);
    if (kz == 1) {
        #pragma unroll
        for (int m = 0; m < 4; m++)
            #pragma unroll
            for (int o = 0; o < 8; o++)
                sP[(ty * 4 + m) * 64 + ob + o] = acc[m][o];
    }
    __syncthreads();

    if (kz == 0) {
        #pragma unroll
        for (int m = 0; m < 4; m++) {
            #pragma unroll
            for (int o = 0; o < 8; o++) {
                const unsigned long long p = sP[(ty * 4 + m) * 64 + ob + o];
                asm("add.rn.f32x2 %0, %0, %1;" : "+l"(acc[m][o]) : "l"(p));
            }
        }
        // --- epilogue: ReLU + store (two float4 per node row) ---
        #pragma unroll
        for (int m = 0; m < 4; m++) {
            float lo[8], hi[8];
            #pragma unroll
            for (int o = 0; o < 8; o++)
                asm("mov.b64 {%0, %1}, %2;" : "=f"(lo[o]), "=f"(hi[o]) : "l"(acc[m][o]));
            const int g0 = node0 + nb + m * 2;
            if (g0 < N_NODES) {
                float4 v0 = make_float4(fmaxf(lo[0],0.f), fmaxf(lo[1],0.f),
                                        fmaxf(lo[2],0.f), fmaxf(lo[3],0.f));
                float4 v1 = make_float4(fmaxf(lo[4],0.f), fmaxf(lo[5],0.f),
                                        fmaxf(lo[6],0.f), fmaxf(lo[7],0.f));
                float4* po = reinterpret_cast<float4*>(out + (size_t)g0*D + ob);
                po[0] = v0; po[1] = v1;
            }
            if (g0 + 1 < N_NODES) {
                float4 v0 = make_float4(fmaxf(hi[0],0.f), fmaxf(hi[1],0.f),
                                        fmaxf(hi[2],0.f), fmaxf(hi[3],0.f));
                float4 v1 = make_float4(fmaxf(hi[4],0.f), fmaxf(hi[5],0.f),
                                        fmaxf(hi[6],0.f), fmaxf(hi[7],0.f));
                float4* po = reinterpret_cast<float4*>(out + (size_t)(g0+1)*D + ob);
                po[0] = v0; po[1] = v1;
            }
        }
    }
}

// ---------------------------------------------------------------------------
extern "C" void kernel_launch(void* const* d_in, const int* in_sizes, int n_in,
                              void* d_out, int out_size)
{
    const float* x  = (const float*)d_in[0];
    const int*   ei = (const int*)d_in[1];     // int32 (JAX x64 disabled)
    const float* Wl = (const float*)d_in[2];
    const float* bl = (const float*)d_in[3];
    const float* Wr = (const float*)d_in[4];
    float* out = (float*)d_out;

    const int smem_bytes = (K2 * WPAD + K2 * APAD) * sizeof(float);   // ~100 KB
    cudaFuncSetAttribute(out_kernel, cudaFuncAttributeMaxDynamicSharedMemorySize, smem_bytes);

    zero_kernel<<<(N_NODES + 255) / 256, 256>>>();
    fill_kernel<<<(N_EDGES + 255) / 256, 256>>>(ei);
    gather_kernel<<<N_NODES / 16, 256>>>(x, ei);   // 2 nodes/warp * 8 warps
    out_kernel<<<(N_NODES + 127) / 128, 256, smem_bytes>>>(x, Wl, bl, Wr, out);
}

// round 15
// speedup vs baseline: 1.2250x; 1.2250x over previous
#include <cuda_runtime.h>
#include <cstdint>

#define N_NODES 100000
#define N_EDGES 1000000
#define D 64
#define CAP 64           // padded CSR slots/node (Poisson(10): P(deg>64)~1e-30; fallback exists)

// Scratch (device globals — no allocations allowed)
__device__ __align__(16) float g_mean[N_NODES * D];
__device__ int g_cnt[N_NODES];
__device__ __align__(16) int g_csr[N_NODES * CAP];

// ---------------------------------------------------------------------------
// Kernel 1: zero degree counters
// ---------------------------------------------------------------------------
__global__ __launch_bounds__(256) void zero_kernel() {
    const int i = blockIdx.x * 256 + threadIdx.x;
    if (i < N_NODES) g_cnt[i] = 0;
}

// ---------------------------------------------------------------------------
// Kernel 2: CSR fill (1 edge/thread — measured best)
// ---------------------------------------------------------------------------
__global__ __launch_bounds__(256) void fill_kernel(const int* __restrict__ ei) {
    const int e = blockIdx.x * 256 + threadIdx.x;
    if (e >= N_EDGES) return;
    const int dst = __ldg(ei + N_EDGES + e);
    const int src = __ldg(ei + e);
    const int pos = atomicAdd(g_cnt + dst, 1);
    if (pos < CAP) g_csr[dst * CAP + pos] = src;
}

// ---------------------------------------------------------------------------
// Kernel 3: gather (round-5 form). Half-warp per node, LDG.128 streams,
// register accumulation, single mean-row write. Inline overflow fallback.
// ---------------------------------------------------------------------------
__global__ __launch_bounds__(256) void gather_kernel(const float* __restrict__ x,
                                                     const int* __restrict__ ei) {
    const int warp = blockIdx.x * 8 + (threadIdx.x >> 5);
    const int lane = threadIdx.x & 31;
    const int sub  = lane >> 4;
    const int j    = lane & 15;
    const int node = warp * 2 + sub;      // grid covers exactly N_NODES

    const int cnt  = g_cnt[node];
    const float r  = 1.0f / (float)(cnt > 1 ? cnt : 1);
    const float4* x4 = reinterpret_cast<const float4*>(x);

    float4 acc = make_float4(0.f, 0.f, 0.f, 0.f);
    if (cnt <= CAP) {
        const int4* row = reinterpret_cast<const int4*>(g_csr + node * CAP);
        for (int e0 = 0; e0 < cnt; e0 += 4) {
            const int4 s = __ldg(row + (e0 >> 2));   // broadcast in half-warp
            const int rem = cnt - e0;
            float4 v0 = __ldg(x4 + (size_t)s.x * 16 + j);
            float4 v1, v2, v3;
            if (rem > 1) v1 = __ldg(x4 + (size_t)s.y * 16 + j);
            if (rem > 2) v2 = __ldg(x4 + (size_t)s.z * 16 + j);
            if (rem > 3) v3 = __ldg(x4 + (size_t)s.w * 16 + j);
            acc.x += v0.x; acc.y += v0.y; acc.z += v0.z; acc.w += v0.w;
            if (rem > 1) { acc.x += v1.x; acc.y += v1.y; acc.z += v1.z; acc.w += v1.w; }
            if (rem > 2) { acc.x += v2.x; acc.y += v2.y; acc.z += v2.z; acc.w += v2.w; }
            if (rem > 3) { acc.x += v3.x; acc.y += v3.y; acc.z += v3.z; acc.w += v3.w; }
        }
    } else {
        for (int e = 0; e < N_EDGES; e++) {          // ~never taken
            if (__ldg(ei + N_EDGES + e) == node) {
                float4 v = __ldg(x4 + (size_t)__ldg(ei + e) * 16 + j);
                acc.x += v.x; acc.y += v.y; acc.z += v.z; acc.w += v.w;
            }
        }
    }
    acc.x *= r; acc.y *= r; acc.z *= r; acc.w *= r;
    reinterpret_cast<float4*>(g_mean)[(size_t)node * 16 + j] = acc;
}

// ---------------------------------------------------------------------------
// Kernel 4: warp-level tf32 tensor-core GEMM (mma.sync m16n8k8, sm_80+ ISA).
// out[128n x 64o] = relu([mean|x] @ [Wl|Wr]^T + b), K = 128.
// fp32 accuracy via 3-pass tf32 split: hi=cvt.rna.tf32(v), lo=v-hi;
// accumulate hi*hi + hi*lo + lo*hi in fp32 (error ~2^-22).
// A fragments read directly from global (full 32B sectors, L2-resident).
// B staged once per CTA in smem hi/lo planes [o][k], stride 132
//  -> fragment LDS bank = (4*o + tid4) mod 32: conflict-free.
// ---------------------------------------------------------------------------
#define BSTRIDE 132

__device__ __forceinline__ uint32_t cvt_tf32(float f) {
    uint32_t r; asm("cvt.rna.tf32.f32 %0, %1;" : "=r"(r) : "f"(f)); return r;
}
__device__ __forceinline__ void mma_tf32(float c[4],
                                         uint32_t a0, uint32_t a1, uint32_t a2, uint32_t a3,
                                         uint32_t b0, uint32_t b1) {
    asm volatile(
        "mma.sync.aligned.m16n8k8.row.col.f32.tf32.tf32.f32 "
        "{%0,%1,%2,%3}, {%4,%5,%6,%7}, {%8,%9}, {%0,%1,%2,%3};"
        : "+f"(c[0]), "+f"(c[1]), "+f"(c[2]), "+f"(c[3])
        : "r"(a0), "r"(a1), "r"(a2), "r"(a3), "r"(b0), "r"(b1));
}

__global__ __launch_bounds__(256, 2) void mma_kernel(
    const float* __restrict__ x,
    const float* __restrict__ Wl,
    const float* __restrict__ bl,
    const float* __restrict__ Wr,
    float* __restrict__ out)
{
    extern __shared__ uint32_t smw[];
    uint32_t* sBhi = smw;                     // [64][BSTRIDE] tf32 hi
    uint32_t* sBlo = smw + 64 * BSTRIDE;      // [64][BSTRIDE] tf32 lo

    const int tid  = threadIdx.x;
    const int wid  = tid >> 5;                // 0..7
    const int lane = tid & 31;
    const int grp  = lane >> 2;               // groupID 0..7
    const int tid4 = lane & 3;                // threadID_in_group
    const int node0 = blockIdx.x * 128;

    // --- stage B = [Wl | Wr] as tf32 hi/lo planes, [o][k] k 0..127 ---
    for (int idx = tid; idx < 64 * 32; idx += 256) {
        const int o = idx >> 5;               // 0..63
        const int q = idx & 31;               // float4 index along k (k = q*4)
        const float4 v = (q < 16)
            ? __ldg(reinterpret_cast<const float4*>(Wl) + o * 16 + q)
            : __ldg(reinterpret_cast<const float4*>(Wr) + o * 16 + (q - 16));
        uint32_t h0 = cvt_tf32(v.x), h1 = cvt_tf32(v.y), h2 = cvt_tf32(v.z), h3 = cvt_tf32(v.w);
        uint32_t l0 = cvt_tf32(v.x - __uint_as_float(h0));
        uint32_t l1 = cvt_tf32(v.y - __uint_as_float(h1));
        uint32_t l2 = cvt_tf32(v.z - __uint_as_float(h2));
        uint32_t l3 = cvt_tf32(v.w - __uint_as_float(h3));
        const int base = o * BSTRIDE + q * 4;      // 16B-aligned (132 % 4 == 0)
        asm volatile("st.shared.v4.b32 [%0], {%1,%2,%3,%4};"
                     :: "r"((uint32_t)__cvta_generic_to_shared(sBhi + base)),
                        "r"(h0), "r"(h1), "r"(h2), "r"(h3) : "memory");
        asm volatile("st.shared.v4.b32 [%0], {%1,%2,%3,%4};"
                     :: "r"((uint32_t)__cvta_generic_to_shared(sBlo + base)),
                        "r"(l0), "r"(l1), "r"(l2), "r"(l3) : "memory");
    }
    __syncthreads();

    // --- A row offsets for this thread's fragments (clamped for tail CTA) ---
    const int r0 = node0 + wid * 16 + grp;
    const int r1 = r0 + 8;
    const size_t off0 = (size_t)(r0 < N_NODES ? r0 : N_NODES - 1) * D;
    const size_t off1 = (size_t)(r1 < N_NODES ? r1 : N_NODES - 1) * D;

    float c[8][4];
    #pragma unroll
    for (int nt = 0; nt < 8; nt++)
        #pragma unroll
        for (int i = 0; i < 4; i++) c[nt][i] = 0.f;

    // --- mainloop: 16 k-steps of 8 (s<8 -> mean/Wl half, s>=8 -> x/Wr half) ---
    #pragma unroll 2
    for (int s = 0; s < 16; s++) {
        const float* As = (s < 8) ? g_mean : x;
        const int kk = (s & 7) * 8;
        const float va0 = __ldg(As + off0 + kk + tid4);
        const float va1 = __ldg(As + off1 + kk + tid4);
        const float va2 = __ldg(As + off0 + kk + tid4 + 4);
        const float va3 = __ldg(As + off1 + kk + tid4 + 4);
        const uint32_t ah0 = cvt_tf32(va0), ah1 = cvt_tf32(va1);
        const uint32_t ah2 = cvt_tf32(va2), ah3 = cvt_tf32(va3);
        const uint32_t al0 = cvt_tf32(va0 - __uint_as_float(ah0));
        const uint32_t al1 = cvt_tf32(va1 - __uint_as_float(ah1));
        const uint32_t al2 = cvt_tf32(va2 - __uint_as_float(ah2));
        const uint32_t al3 = cvt_tf32(va3 - __uint_as_float(ah3));

        const int bcol = s * 8 + tid4;             // global k for B fragments
        #pragma unroll
        for (int nt = 0; nt < 8; nt++) {
            const int bb = (nt * 8 + grp) * BSTRIDE + bcol;
            const uint32_t bh0 = sBhi[bb], bh1 = sBhi[bb + 4];
            const uint32_t bl0 = sBlo[bb], bl1 = sBlo[bb + 4];
            mma_tf32(c[nt], ah0, ah1, ah2, ah3, bh0, bh1);   // hi*hi
            mma_tf32(c[nt], ah0, ah1, ah2, ah3, bl0, bl1);   // hi*lo
            mma_tf32(c[nt], al0, al1, al2, al3, bh0, bh1);   // lo*hi
        }
    }

    // --- epilogue: +bias, ReLU, store float2 pairs ---
    const int colb = 2 * tid4;
    #pragma unroll
    for (int nt = 0; nt < 8; nt++) {
        const int col = nt * 8 + colb;
        const float2 b2 = __ldg(reinterpret_cast<const float2*>(bl + col));
        if (r0 < N_NODES) {
            float2 v;
            v.x = fmaxf(c[nt][0] + b2.x, 0.f);
            v.y = fmaxf(c[nt][1] + b2.y, 0.f);
            *reinterpret_cast<float2*>(out + (size_t)r0 * D + col) = v;
        }
        if (r1 < N_NODES) {
            float2 v;
            v.x = fmaxf(c[nt][2] + b2.x, 0.f);
            v.y = fmaxf(c[nt][3] + b2.y, 0.f);
            *reinterpret_cast<float2*>(out + (size_t)r1 * D + col) = v;
        }
    }
}

// ---------------------------------------------------------------------------
extern "C" void kernel_launch(void* const* d_in, const int* in_sizes, int n_in,
                              void* d_out, int out_size)
{
    const float* x  = (const float*)d_in[0];
    const int*   ei = (const int*)d_in[1];     // int32 (JAX x64 disabled)
    const float* Wl = (const float*)d_in[2];
    const float* bl = (const float*)d_in[3];
    const float* Wr = (const float*)d_in[4];
    float* out = (float*)d_out;

    const int smem_bytes = 2 * 64 * BSTRIDE * sizeof(uint32_t);   // 67.6 KB
    cudaFuncSetAttribute(mma_kernel, cudaFuncAttributeMaxDynamicSharedMemorySize, smem_bytes);

    zero_kernel<<<(N_NODES + 255) / 256, 256>>>();
    fill_kernel<<<(N_EDGES + 255) / 256, 256>>>(ei);
    gather_kernel<<<N_NODES / 16, 256>>>(x, ei);   // 2 nodes/warp * 8 warps
    mma_kernel<<<(N_NODES + 127) / 128, 256, smem_bytes>>>(x, Wl, bl, Wr, out);
}